// round 1
// baseline (speedup 1.0000x reference)
#include <cuda_runtime.h>

#define BB 8
#define CC 256
#define EE 128
#define NN 3136          // 56*56
#define NV (NN/4)        // 784

__device__ float g_a[CC];
__device__ float g_c0;
__device__ float g_s[BB * NN];
__device__ float g_t[BB * CC];
__device__ float g_d[BB * CC];

// K0: a[c] = sum_e wq_c[e]*Wq[e,c] + wk_c[e]*Wk[e,c];  c0 = wq_c.bq + wk_c.bk
__global__ void k0_fold(const float* __restrict__ Wq, const float* __restrict__ bq,
                        const float* __restrict__ Wk, const float* __restrict__ bk,
                        const float* __restrict__ Wcat) {
    int c = threadIdx.x;  // 256 threads
    float acc = 0.f;
    #pragma unroll 8
    for (int e = 0; e < EE; e++)
        acc = fmaf(Wcat[e], Wq[e * CC + c], fmaf(Wcat[EE + e], Wk[e * CC + c], acc));
    g_a[c] = acc;
    if (c == 0) {
        float c0 = 0.f;
        for (int e = 0; e < EE; e++)
            c0 = fmaf(Wcat[e], bq[e], fmaf(Wcat[EE + e], bk[e], c0));
        g_c0 = c0;
    }
}

// K1a: s[b,n] = relu(sum_c a[c]*x[b,c,n] + c0). Coalesced over n.
__global__ void k1a_s(const float* __restrict__ x) {
    __shared__ float sa[CC];
    int tid = threadIdx.x;
    sa[tid] = g_a[tid];
    __syncthreads();
    int b = blockIdx.y;
    int n = blockIdx.x * blockDim.x + tid;
    if (n >= NN) return;
    const float* xb = x + (size_t)b * CC * NN + n;
    float y = g_c0;
    #pragma unroll 8
    for (int c = 0; c < CC; c++)
        y = fmaf(sa[c], xb[(size_t)c * NN], y);
    g_s[b * NN + n] = fmaxf(y, 0.f);
}

// K1b: t[b,c] = (1/N) sum_n s[b,n]*x[b,c,n]. One block per (b,c), vectorized.
__global__ void k1b_t(const float* __restrict__ x) {
    int bc = blockIdx.x;         // b*CC + c
    int b = bc >> 8;
    int tid = threadIdx.x;       // 128 threads
    const float4* x4 = (const float4*)(x + (size_t)bc * NN);
    const float4* s4 = (const float4*)(g_s + (size_t)b * NN);
    float acc = 0.f;
    for (int i = tid; i < NV; i += 128) {
        float4 xv = x4[i];
        float4 sv = s4[i];
        acc += xv.x * sv.x + xv.y * sv.y + xv.z * sv.z + xv.w * sv.w;
    }
    // warp reduce
    #pragma unroll
    for (int o = 16; o > 0; o >>= 1)
        acc += __shfl_down_sync(0xFFFFFFFFu, acc, o);
    __shared__ float red[4];
    if ((tid & 31) == 0) red[tid >> 5] = acc;
    __syncthreads();
    if (tid == 0)
        g_t[bc] = (red[0] + red[1] + red[2] + red[3]) * (1.0f / NN);
}

// K2: per-b: sbar, m[e], d[c]. One block per b, 256 threads.
__global__ void k2_md(const float* __restrict__ Wv, const float* __restrict__ bv,
                      const float* __restrict__ Wexp, const float* __restrict__ bexp) {
    int b = blockIdx.x;
    int tid = threadIdx.x;
    __shared__ float st[CC];
    __shared__ float sm[EE];
    __shared__ float red[256];
    __shared__ float sbar_s;
    st[tid] = g_t[b * CC + tid];
    // sbar = mean of s[b,:]
    float acc = 0.f;
    for (int n = tid; n < NN; n += 256) acc += g_s[b * NN + n];
    red[tid] = acc;
    __syncthreads();
    #pragma unroll
    for (int o = 128; o > 0; o >>= 1) {
        if (tid < o) red[tid] += red[tid + o];
        __syncthreads();
    }
    if (tid == 0) sbar_s = red[0] * (1.0f / NN);
    __syncthreads();
    float sbar = sbar_s;
    if (tid < EE) {
        float m = bv[tid] * sbar;
        #pragma unroll 8
        for (int c = 0; c < CC; c++)
            m = fmaf(Wv[tid * CC + c], st[c], m);
        sm[tid] = m;
    }
    __syncthreads();
    float dd = bexp[tid];
    #pragma unroll 8
    for (int e = 0; e < EE; e++)
        dd = fmaf(Wexp[tid * EE + e], sm[e], dd);
    g_d[b * CC + tid] = dd;
}

// K3: out[b,c,n] = x[b,c,n] + d[b,c]. float4 vectorized.
__global__ void k3_out(const float* __restrict__ x, float* __restrict__ out) {
    int i = blockIdx.x * blockDim.x + threadIdx.x;  // float4 index
    const int total = BB * CC * NV;
    if (i >= total) return;
    int row = i / NV;   // b*CC + c
    float dv = g_d[row];
    float4 xv = ((const float4*)x)[i];
    float4 o;
    o.x = xv.x + dv;
    o.y = xv.y + dv;
    o.z = xv.z + dv;
    o.w = xv.w + dv;
    ((float4*)out)[i] = o;
}

extern "C" void kernel_launch(void* const* d_in, const int* in_sizes, int n_in,
                              void* d_out, int out_size) {
    const float* x    = (const float*)d_in[0];
    const float* Wq   = (const float*)d_in[1];
    const float* bq   = (const float*)d_in[2];
    const float* Wk   = (const float*)d_in[3];
    const float* bk   = (const float*)d_in[4];
    const float* Wv   = (const float*)d_in[5];
    const float* bv   = (const float*)d_in[6];
    const float* Wcat = (const float*)d_in[7];
    const float* Wexp = (const float*)d_in[8];
    const float* bexp = (const float*)d_in[9];
    float* out = (float*)d_out;

    k0_fold<<<1, 256>>>(Wq, bq, Wk, bk, Wcat);

    dim3 g1((NN + 255) / 256, BB);
    k1a_s<<<g1, 256>>>(x);

    k1b_t<<<BB * CC, 128>>>(x);

    k2_md<<<BB, 256>>>(Wv, bv, Wexp, bexp);

    int total4 = BB * CC * NV;
    k3_out<<<(total4 + 255) / 256, 256>>>(x, out);
}

// round 2
// speedup vs baseline: 1.8663x; 1.8663x over previous
#include <cuda_runtime.h>

#define BB 8
#define CC 256
#define EE 128
#define NN 3136          // 56*56
#define NV (NN/4)        // 784

__device__ float g_a[CC];
__device__ float g_c0;
__device__ float g_s[BB * NN];
__device__ float g_sbar[BB];     // mean of s[b,:]
__device__ float g_t[BB * CC];
__device__ float g_m[BB * EE];
__device__ float g_d[BB * CC];

// K0: a[c] = sum_e wq_c[e]*Wq[e,c] + wk_c[e]*Wk[e,c];  c0 = wq_c.bq + wk_c.bk
__global__ void k0_fold(const float* __restrict__ Wq, const float* __restrict__ bq,
                        const float* __restrict__ Wk, const float* __restrict__ bk,
                        const float* __restrict__ Wcat) {
    int c = threadIdx.x;  // 256 threads
    float acc = 0.f;
    #pragma unroll 8
    for (int e = 0; e < EE; e++)
        acc = fmaf(Wcat[e], Wq[e * CC + c], fmaf(Wcat[EE + e], Wk[e * CC + c], acc));
    g_a[c] = acc;
    if (c == 0) {
        float c0 = 0.f;
        for (int e = 0; e < EE; e++)
            c0 = fmaf(Wcat[e], bq[e], fmaf(Wcat[EE + e], bk[e], c0));
        g_c0 = c0;
    }
}

// K1a: s[b,n] = relu(sum_c a[c]*x[b,c,n] + c0). Coalesced over n.
__global__ void k1a_s(const float* __restrict__ x) {
    __shared__ float sa[CC];
    int tid = threadIdx.x;
    sa[tid] = g_a[tid];
    __syncthreads();
    int b = blockIdx.y;
    int n = blockIdx.x * blockDim.x + tid;
    if (n >= NN) return;
    const float* xb = x + (size_t)b * CC * NN + n;
    float y = g_c0;
    #pragma unroll 8
    for (int c = 0; c < CC; c++)
        y = fmaf(sa[c], xb[(size_t)c * NN], y);
    g_s[b * NN + n] = fmaxf(y, 0.f);
}

// K1b: t[b,c] = (1/N) sum_n s[b,n]*x[b,c,n]. One block per (b,c).
//      Blocks with c==0 additionally produce sbar[b] = mean(s[b,:]) for free.
__global__ void k1b_t(const float* __restrict__ x) {
    int bc = blockIdx.x;         // b*CC + c
    int b = bc >> 8;
    bool do_sbar = ((bc & 255) == 0);
    int tid = threadIdx.x;       // 128 threads
    const float4* x4 = (const float4*)(x + (size_t)bc * NN);
    const float4* s4 = (const float4*)(g_s + (size_t)b * NN);
    float acc = 0.f;
    float sacc = 0.f;
    for (int i = tid; i < NV; i += 128) {
        float4 xv = x4[i];
        float4 sv = s4[i];
        acc += xv.x * sv.x + xv.y * sv.y + xv.z * sv.z + xv.w * sv.w;
        if (do_sbar) sacc += sv.x + sv.y + sv.z + sv.w;
    }
    #pragma unroll
    for (int o = 16; o > 0; o >>= 1) {
        acc  += __shfl_down_sync(0xFFFFFFFFu, acc, o);
        sacc += __shfl_down_sync(0xFFFFFFFFu, sacc, o);
    }
    __shared__ float red[4], sred[4];
    if ((tid & 31) == 0) { red[tid >> 5] = acc; sred[tid >> 5] = sacc; }
    __syncthreads();
    if (tid == 0) {
        g_t[bc] = (red[0] + red[1] + red[2] + red[3]) * (1.0f / NN);
        if (do_sbar)
            g_sbar[b] = (sred[0] + sred[1] + sred[2] + sred[3]) * (1.0f / NN);
    }
}

// K2a: m[b,e] = sum_c Wv[e,c]*t[b,c] + bv[e]*sbar[b]. One warp per (b,e).
__global__ void k2a_m(const float* __restrict__ Wv, const float* __restrict__ bv) {
    int b = blockIdx.y;
    int tid = threadIdx.x;       // 256 threads, 8 warps
    int w = tid >> 5, lane = tid & 31;
    __shared__ float st[CC];
    st[tid] = g_t[b * CC + tid];
    __syncthreads();
    int e = blockIdx.x * 8 + w;  // blockIdx.x in [0,16)
    const float* wr = Wv + (size_t)e * CC;
    float acc = 0.f;
    #pragma unroll
    for (int k = 0; k < 8; k++) {
        int c = lane + 32 * k;
        acc = fmaf(wr[c], st[c], acc);
    }
    #pragma unroll
    for (int o = 16; o > 0; o >>= 1)
        acc += __shfl_down_sync(0xFFFFFFFFu, acc, o);
    if (lane == 0)
        g_m[b * EE + e] = acc + bv[e] * g_sbar[b];
}

// K2b: d[b,c] = sum_e Wexp[c,e]*m[b,e] + bexp[c]. One warp per (b,c).
__global__ void k2b_d(const float* __restrict__ Wexp, const float* __restrict__ bexp) {
    int b = blockIdx.y;
    int tid = threadIdx.x;       // 256 threads, 8 warps
    int w = tid >> 5, lane = tid & 31;
    __shared__ float sm[EE];
    if (tid < EE) sm[tid] = g_m[b * EE + tid];
    __syncthreads();
    int c = blockIdx.x * 8 + w;  // blockIdx.x in [0,32)
    const float* wr = Wexp + (size_t)c * EE;
    float acc = 0.f;
    #pragma unroll
    for (int k = 0; k < 4; k++) {
        int e = lane + 32 * k;
        acc = fmaf(wr[e], sm[e], acc);
    }
    #pragma unroll
    for (int o = 16; o > 0; o >>= 1)
        acc += __shfl_down_sync(0xFFFFFFFFu, acc, o);
    if (lane == 0)
        g_d[b * CC + c] = acc + bexp[c];
}

// K3: out[b,c,n] = x[b,c,n] + d[b,c]. float4 vectorized.
__global__ void k3_out(const float* __restrict__ x, float* __restrict__ out) {
    int i = blockIdx.x * blockDim.x + threadIdx.x;  // float4 index
    const int total = BB * CC * NV;
    if (i >= total) return;
    int row = i / NV;   // b*CC + c
    float dv = g_d[row];
    float4 xv = ((const float4*)x)[i];
    float4 o;
    o.x = xv.x + dv;
    o.y = xv.y + dv;
    o.z = xv.z + dv;
    o.w = xv.w + dv;
    ((float4*)out)[i] = o;
}

extern "C" void kernel_launch(void* const* d_in, const int* in_sizes, int n_in,
                              void* d_out, int out_size) {
    const float* x    = (const float*)d_in[0];
    const float* Wq   = (const float*)d_in[1];
    const float* bq   = (const float*)d_in[2];
    const float* Wk   = (const float*)d_in[3];
    const float* bk   = (const float*)d_in[4];
    const float* Wv   = (const float*)d_in[5];
    const float* bv   = (const float*)d_in[6];
    const float* Wcat = (const float*)d_in[7];
    const float* Wexp = (const float*)d_in[8];
    const float* bexp = (const float*)d_in[9];
    float* out = (float*)d_out;

    k0_fold<<<1, 256>>>(Wq, bq, Wk, bk, Wcat);

    dim3 g1((NN + 255) / 256, BB);
    k1a_s<<<g1, 256>>>(x);

    k1b_t<<<BB * CC, 128>>>(x);

    k2a_m<<<dim3(16, BB), 256>>>(Wv, bv);
    k2b_d<<<dim3(32, BB), 256>>>(Wexp, bexp);

    int total4 = BB * CC * NV;
    k3_out<<<(total4 + 255) / 256, 256>>>(x, out);
}